// round 1
// baseline (speedup 1.0000x reference)
#include <cuda_runtime.h>
#include <cstdint>

// Problem constants (fixed shapes for this dataset)
#define NTOK   2048
#define EMB    512            // 2*WDIM
#define HD     512
#define NSEG   32
#define SEGLEN 64             // NTOK / NSEG
#define MAXM   40960          // >= 40770 chunks

// Positional table row offsets inside g_Tpos
#define OFF_START 0
#define OFF_END   2048
#define OFF_LEN   (2048 + 2049)          // 4097
#define OFF_MID   (2048 + 2049 + 21)     // 4118
#define TROWS     (2048 + 2049 + 21 + 4096) // 8214

// -------- device scratch (globals are the sanctioned scratch mechanism) -----
__device__ float g_csum[(NTOK + 1) * EMB];       // prefix sums of token embs
__device__ float g_csumW[(NTOK + 1) * HD];       // csum @ dan_w0
__device__ float g_Tpos[(size_t)TROWS * HD];     // positional-feature @ ws_w0 tables
__device__ float g_phrase[(size_t)MAXM * HD];    // DAN output per chunk
__device__ float g_segsum[NSEG * EMB];
__device__ float g_segoff[NSEG * EMB];
__device__ float g_partial[MAXM * 4];            // 4 N-block partial dots per chunk

// ----------------------------------------------------------------------------
__device__ __forceinline__ float embval(const int* __restrict__ sent,
                                        const int* __restrict__ tags,
                                        const float* __restrict__ Wwrd,
                                        const float* __restrict__ Wpos,
                                        int t, int col) {
    if (col < 256) return Wpos[tags[t] * 256 + col];
    return Wwrd[(size_t)sent[t] * 256 + (col - 256)];
}

// Phase A: per-segment column sums
__global__ void k_segsum(const int* __restrict__ sent, const int* __restrict__ tags,
                         const float* __restrict__ Wwrd, const float* __restrict__ Wpos) {
    int seg = blockIdx.x;
    int col = blockIdx.y * 256 + threadIdx.x;
    float acc = 0.f;
    int t0 = seg * SEGLEN;
    for (int t = t0; t < t0 + SEGLEN; t++) acc += embval(sent, tags, Wwrd, Wpos, t, col);
    g_segsum[seg * EMB + col] = acc;
}

// Phase B: exclusive scan of segment sums per column (1 block, 512 threads)
__global__ void k_segscan() {
    int col = threadIdx.x;
    float run = 0.f;
    for (int s = 0; s < NSEG; s++) {
        float v = g_segsum[s * EMB + col];
        g_segoff[s * EMB + col] = run;
        run += v;
    }
}

// Phase C: write inclusive prefix-sum rows (csum[0] = 0, csum[t+1] = sum_{<=t})
__global__ void k_csum(const int* __restrict__ sent, const int* __restrict__ tags,
                       const float* __restrict__ Wwrd, const float* __restrict__ Wpos) {
    int seg = blockIdx.x;
    int col = blockIdx.y * 256 + threadIdx.x;
    float acc = g_segoff[seg * EMB + col];
    if (seg == 0) g_csum[col] = 0.f;
    int t0 = seg * SEGLEN;
    for (int t = t0; t < t0 + SEGLEN; t++) {
        acc += embval(sent, tags, Wwrd, Wpos, t, col);
        g_csum[(size_t)(t + 1) * EMB + col] = acc;
    }
}

// ----------------------------------------------------------------------------
// K2: g_csumW = g_csum[2049,512] @ dan_w0[512,512]   (plain SGEMM 128x64 tile)
__global__ void __launch_bounds__(256) k_sgemm_csumW(const float* __restrict__ W0, int M) {
    __shared__ float As[16][132];
    __shared__ float Bs[16][64];
    int tid = threadIdx.x, tx = tid & 15, ty = tid >> 4;
    int mb = blockIdx.x * 128, nb = blockIdx.y * 64;
    float acc[8][4] = {};
    for (int k0 = 0; k0 < 512; k0 += 16) {
#pragma unroll
        for (int i = 0; i < 2; i++) {
            int r = (tid >> 2) + i * 64;
            int c = (tid & 3) * 4;
            int gr = mb + r;
            float4 v = make_float4(0.f, 0.f, 0.f, 0.f);
            if (gr < M) v = *(const float4*)(g_csum + (size_t)gr * 512 + k0 + c);
            As[c + 0][r] = v.x; As[c + 1][r] = v.y; As[c + 2][r] = v.z; As[c + 3][r] = v.w;
        }
        {
            int r = tid >> 4, c = (tid & 15) * 4;
            *(float4*)&Bs[r][c] = *(const float4*)(W0 + (size_t)(k0 + r) * 512 + nb + c);
        }
        __syncthreads();
#pragma unroll
        for (int k = 0; k < 16; k++) {
            float a[8];
            *(float4*)&a[0] = *(const float4*)&As[k][ty * 8];
            *(float4*)&a[4] = *(const float4*)&As[k][ty * 8 + 4];
            float4 bv = *(const float4*)&Bs[k][tx * 4];
#pragma unroll
            for (int i = 0; i < 8; i++) {
                acc[i][0] += a[i] * bv.x; acc[i][1] += a[i] * bv.y;
                acc[i][2] += a[i] * bv.z; acc[i][3] += a[i] * bv.w;
            }
        }
        __syncthreads();
    }
#pragma unroll
    for (int i = 0; i < 8; i++) {
        int gr = mb + ty * 8 + i;
        if (gr < M) {
            float4 o = make_float4(acc[i][0], acc[i][1], acc[i][2], acc[i][3]);
            *(float4*)(g_csumW + (size_t)gr * 512 + nb + tx * 4) = o;
        }
    }
}

// ----------------------------------------------------------------------------
// K3: positional tables  T[row] = pe(v)(32) @ ws_w0[woff:woff+32, :]
__global__ void k_tables(const float* __restrict__ Ww0) {
    __shared__ float pe[32];
    int row = blockIdx.x;
    int col = blockIdx.y * 256 + threadIdx.x;
    float v; int woff;
    if (row < 2048)      { v = (float)row;               woff = 512; }
    else if (row < 4097) { v = (float)(row - 2048);      woff = 544; }
    else if (row < 4118) { v = (float)(row - 4097);      woff = 576; }
    else                 { v = 0.5f * (float)(row - 4118); woff = 608; }
    if (threadIdx.x < 32) {
        int d = threadIdx.x, k = d & 15;
        float freq = expf(-logf(10000.0f) * ((float)(2 * k) / 32.0f));
        float ang = v * freq;
        pe[d] = (d < 16) ? sinf(ang) : cosf(ang);
    }
    __syncthreads();
    float s = 0.f;
#pragma unroll
    for (int d = 0; d < 32; d++) s += pe[d] * Ww0[(size_t)(woff + d) * 512 + col];
    g_Tpos[(size_t)row * 512 + col] = s;
}

// ----------------------------------------------------------------------------
// K5: phrase = relu( relu((csumW[e]-csumW[s])/len + b0) @ dan_w1 + b1 )
//     A (h) is built on the fly from csumW during the A-tile load.
__global__ void __launch_bounds__(256) k_gemm2(const int* __restrict__ sst, const int* __restrict__ sln,
                                               const float* __restrict__ b0,
                                               const float* __restrict__ W1,
                                               const float* __restrict__ b1, int M) {
    __shared__ float As[16][132];
    __shared__ float Bs[16][64];
    int tid = threadIdx.x, tx = tid & 15, ty = tid >> 4;
    int mb = blockIdx.x * 128, nb = blockIdx.y * 64;
    float acc[8][4] = {};
    for (int k0 = 0; k0 < 512; k0 += 16) {
#pragma unroll
        for (int i = 0; i < 2; i++) {
            int r = (tid >> 2) + i * 64;
            int c = (tid & 3) * 4;
            int gr = mb + r;
            float4 v = make_float4(0.f, 0.f, 0.f, 0.f);
            if (gr < M) {
                int s = sst[gr], l = sln[gr];
                float inv = 1.f / (float)l;
                float4 ve = *(const float4*)(g_csumW + (size_t)(s + l) * 512 + k0 + c);
                float4 vs = *(const float4*)(g_csumW + (size_t)s * 512 + k0 + c);
                float4 bb = *(const float4*)(b0 + k0 + c);
                v.x = fmaxf((ve.x - vs.x) * inv + bb.x, 0.f);
                v.y = fmaxf((ve.y - vs.y) * inv + bb.y, 0.f);
                v.z = fmaxf((ve.z - vs.z) * inv + bb.z, 0.f);
                v.w = fmaxf((ve.w - vs.w) * inv + bb.w, 0.f);
            }
            As[c + 0][r] = v.x; As[c + 1][r] = v.y; As[c + 2][r] = v.z; As[c + 3][r] = v.w;
        }
        {
            int r = tid >> 4, c = (tid & 15) * 4;
            *(float4*)&Bs[r][c] = *(const float4*)(W1 + (size_t)(k0 + r) * 512 + nb + c);
        }
        __syncthreads();
#pragma unroll
        for (int k = 0; k < 16; k++) {
            float a[8];
            *(float4*)&a[0] = *(const float4*)&As[k][ty * 8];
            *(float4*)&a[4] = *(const float4*)&As[k][ty * 8 + 4];
            float4 bv = *(const float4*)&Bs[k][tx * 4];
#pragma unroll
            for (int i = 0; i < 8; i++) {
                acc[i][0] += a[i] * bv.x; acc[i][1] += a[i] * bv.y;
                acc[i][2] += a[i] * bv.z; acc[i][3] += a[i] * bv.w;
            }
        }
        __syncthreads();
    }
    float4 bb = *(const float4*)(b1 + nb + tx * 4);
#pragma unroll
    for (int i = 0; i < 8; i++) {
        int gr = mb + ty * 8 + i;
        if (gr < M) {
            float4 o;
            o.x = fmaxf(acc[i][0] + bb.x, 0.f);
            o.y = fmaxf(acc[i][1] + bb.y, 0.f);
            o.z = fmaxf(acc[i][2] + bb.z, 0.f);
            o.w = fmaxf(acc[i][3] + bb.w, 0.f);
            *(float4*)(g_phrase + (size_t)gr * 512 + nb + tx * 4) = o;
        }
    }
}

// ----------------------------------------------------------------------------
// K6: partial = sum_{n in Nblock} relu(phrase@ws_w0[:512] + Tpos gathers + ws_b0)[n] * ws_w1[n]
//     128x128 tile, fused epilogue, deterministic per-block partials (no atomics).
__global__ void __launch_bounds__(256) k_gemm3(const float* __restrict__ Ww0,
                                               const float* __restrict__ wb0,
                                               const float* __restrict__ ww1,
                                               const int* __restrict__ sst,
                                               const int* __restrict__ sln, int M) {
    __shared__ float As[16][132];
    __shared__ float Bs[16][128];
    __shared__ float sdot[128][17];
    int tid = threadIdx.x, tx = tid & 15, ty = tid >> 4;
    int mb = blockIdx.x * 128, nb = blockIdx.y * 128;
    float acc[8][8] = {};
    for (int k0 = 0; k0 < 512; k0 += 16) {
#pragma unroll
        for (int i = 0; i < 2; i++) {
            int r = (tid >> 2) + i * 64;
            int c = (tid & 3) * 4;
            int gr = mb + r;
            float4 v = make_float4(0.f, 0.f, 0.f, 0.f);
            if (gr < M) v = *(const float4*)(g_phrase + (size_t)gr * 512 + k0 + c);
            As[c + 0][r] = v.x; As[c + 1][r] = v.y; As[c + 2][r] = v.z; As[c + 3][r] = v.w;
        }
#pragma unroll
        for (int i = 0; i < 2; i++) {
            int r = (tid >> 5) + i * 8;
            int c = (tid & 31) * 4;
            *(float4*)&Bs[r][c] = *(const float4*)(Ww0 + (size_t)(k0 + r) * 512 + nb + c);
        }
        __syncthreads();
#pragma unroll
        for (int k = 0; k < 16; k++) {
            float a[8], b[8];
            *(float4*)&a[0] = *(const float4*)&As[k][ty * 8];
            *(float4*)&a[4] = *(const float4*)&As[k][ty * 8 + 4];
            *(float4*)&b[0] = *(const float4*)&Bs[k][tx * 8];
            *(float4*)&b[4] = *(const float4*)&Bs[k][tx * 8 + 4];
#pragma unroll
            for (int i = 0; i < 8; i++)
#pragma unroll
                for (int j = 0; j < 8; j++) acc[i][j] += a[i] * b[j];
        }
        __syncthreads();
    }
    int n0 = nb + tx * 8;
    float bias[8], w1v[8];
    *(float4*)&bias[0] = *(const float4*)(wb0 + n0);
    *(float4*)&bias[4] = *(const float4*)(wb0 + n0 + 4);
    *(float4*)&w1v[0]  = *(const float4*)(ww1 + n0);
    *(float4*)&w1v[4]  = *(const float4*)(ww1 + n0 + 4);
#pragma unroll
    for (int i = 0; i < 8; i++) {
        int gr = mb + ty * 8 + i;
        float dot = 0.f;
        if (gr < M) {
            int s = sst[gr], l = sln[gr];
            const float* t0 = g_Tpos + (size_t)(OFF_START + s) * 512 + n0;
            const float* t1 = g_Tpos + (size_t)(OFF_END + s + l) * 512 + n0;
            const float* t2 = g_Tpos + (size_t)(OFF_LEN + l) * 512 + n0;
            const float* t3 = g_Tpos + (size_t)(OFF_MID + 2 * s + l) * 512 + n0;
            float p[8];
#pragma unroll
            for (int h = 0; h < 2; h++) {
                float4 a0 = *(const float4*)(t0 + 4 * h);
                float4 a1 = *(const float4*)(t1 + 4 * h);
                float4 a2 = *(const float4*)(t2 + 4 * h);
                float4 a3 = *(const float4*)(t3 + 4 * h);
                p[4 * h + 0] = a0.x + a1.x + a2.x + a3.x;
                p[4 * h + 1] = a0.y + a1.y + a2.y + a3.y;
                p[4 * h + 2] = a0.z + a1.z + a2.z + a3.z;
                p[4 * h + 3] = a0.w + a1.w + a2.w + a3.w;
            }
#pragma unroll
            for (int j = 0; j < 8; j++) {
                float val = fmaxf(acc[i][j] + bias[j] + p[j], 0.f);
                dot += val * w1v[j];
            }
        }
        sdot[ty * 8 + i][tx] = dot;
    }
    __syncthreads();
    if (tid < 128) {
        float s = 0.f;
#pragma unroll
        for (int t = 0; t < 16; t++) s += sdot[tid][t];
        int gr = mb + tid;
        if (gr < M) g_partial[gr * 4 + blockIdx.y] = s;
    }
}

// ----------------------------------------------------------------------------
__global__ void k_final(const float* __restrict__ wb1, float* __restrict__ out, int M) {
    int c = blockIdx.x * 256 + threadIdx.x;
    if (c < M)
        out[c] = g_partial[c * 4 + 0] + g_partial[c * 4 + 1] +
                 g_partial[c * 4 + 2] + g_partial[c * 4 + 3] + wb1[0];
}

// ----------------------------------------------------------------------------
extern "C" void kernel_launch(void* const* d_in, const int* in_sizes, int n_in,
                              void* d_out, int out_size) {
    const int*   sent = (const int*)d_in[0];
    const int*   tags = (const int*)d_in[1];
    const int*   sst  = (const int*)d_in[2];
    const int*   sln  = (const int*)d_in[3];
    const float* Wwrd = (const float*)d_in[4];
    const float* Wpos = (const float*)d_in[5];
    const float* w0   = (const float*)d_in[6];
    const float* b0   = (const float*)d_in[7];
    const float* w1   = (const float*)d_in[8];
    const float* b1   = (const float*)d_in[9];
    const float* ww0  = (const float*)d_in[10];
    const float* wb0  = (const float*)d_in[11];
    const float* ww1  = (const float*)d_in[12];
    const float* wb1  = (const float*)d_in[13];
    float* out = (float*)d_out;
    int M = in_sizes[2];   // number of spans

    // 1) token-embedding prefix sums (segmented scan, 3 tiny kernels)
    k_segsum<<<dim3(NSEG, 2), 256>>>(sent, tags, Wwrd, Wpos);
    k_segscan<<<1, 512>>>();
    k_csum<<<dim3(NSEG, 2), 256>>>(sent, tags, Wwrd, Wpos);

    // 2) csumW = csum @ dan_w0  (replaces the 21 GFLOP span-mean GEMM)
    k_sgemm_csumW<<<dim3((NTOK + 1 + 127) / 128, 8), 256>>>(w0, NTOK + 1);

    // 3) positional-feature @ ws_w0 lookup tables
    k_tables<<<dim3(TROWS, 2), 256>>>(ww0);

    // 4) phrase = relu(relu(span_mean@W0+b0) @ W1 + b1), h built on the fly
    k_gemm2<<<dim3((M + 127) / 128, 8), 256>>>(sst, sln, b0, w1, b1, M);

    // 5) fused scoring GEMM + pos tables + relu + dot(ws_w1) partials
    k_gemm3<<<dim3((M + 127) / 128, 4), 256>>>(ww0, wb0, ww1, sst, sln, M);

    // 6) combine partials + final bias
    k_final<<<(M + 255) / 256, 256>>>(wb1, out, M);
}